// round 6
// baseline (speedup 1.0000x reference)
#include <cuda_runtime.h>

#define NN 50000
#define NE 500000
#define INC 128
#define OC 256      // OUT_CH * HEADS
#define HEADS 4
#define OUTC 64

typedef unsigned long long u64;

// ---------------- scratch (static device globals; no runtime allocation) ----
__device__ __align__(16) float g_Q[NN * OC];
__device__ __align__(16) float g_K[NN * OC];
__device__ __align__(16) float g_V[NN * OC];
__device__ __align__(16) float g_S[NE * HEADS];   // scores, then exp(scores - max)
__device__ __align__(16) float g_agg[NN * OC];
__device__ int   g_src[NE];
__device__ int   g_tgt[NE];
__device__ int   g_counts[NN];
__device__ int   g_cursor[NN];
__device__ int   g_offsets[NN + 1];
__device__ int   g_order[NE];
__device__ unsigned g_maxkey[HEADS];
__device__ float g_Z[HEADS];
__device__ int   g_is64;

// ---------------- helpers ---------------------------------------------------
__device__ __forceinline__ u64 pack_dup(float v) {
    u64 r; asm("mov.b64 %0, {%1,%1};" : "=l"(r) : "f"(v)); return r;
}
__device__ __forceinline__ void fma2(u64 &d, u64 a, u64 b) {
    asm("fma.rn.f32x2 %0, %1, %2, %3;" : "=l"(d) : "l"(a), "l"(b), "l"(d));
}
__device__ __forceinline__ float2 unpack2(u64 v) {
    float2 f; asm("mov.b64 {%0,%1}, %2;" : "=f"(f.x), "=f"(f.y) : "l"(v)); return f;
}
__device__ __forceinline__ unsigned fflip(float f) {
    unsigned u = __float_as_uint(f);
    return u ^ ((u >> 31) ? 0xFFFFFFFFu : 0x80000000u);
}
__device__ __forceinline__ float funflip(unsigned u) {
    return __uint_as_float(u ^ ((u >> 31) ? 0x80000000u : 0xFFFFFFFFu));
}

// ---------------- K0: init + edge-index dtype probe -------------------------
__global__ void k_init(const void* ei) {
    int i = blockIdx.x * blockDim.x + threadIdx.x;
    if (i < NN) { g_counts[i] = 0; g_cursor[i] = 0; }
    if (i < HEADS) { g_maxkey[i] = 0u; g_Z[i] = 0.0f; }
    if (i == 0) {
        // If the buffer holds int64 node ids, the first 64 int64 reads are all
        // in [0, NN). If it holds int32 ids, an int64 read combines two random
        // ids -> almost surely >= 2^32. (64 int64 reads = 512B, in-bounds
        // for either layout since the int32 layout is 4MB.)
        const long long* p = (const long long*)ei;
        int ok = 1;
        for (int j = 0; j < 64; j++) {
            long long v = p[j];
            if (v < 0 || v >= NN) { ok = 0; break; }
        }
        g_is64 = ok;
    }
}

// ---------------- K0b: decode edge index to int32 + histogram ---------------
__global__ void k_decode(const void* ei) {
    int e = blockIdx.x * blockDim.x + threadIdx.x;
    if (e >= NE) return;
    int s, t;
    if (g_is64) {
        const long long* p = (const long long*)ei;
        s = (int)p[e];
        t = (int)p[NE + e];
    } else {
        const int* p = (const int*)ei;
        s = p[e];
        t = p[NE + e];
    }
    g_src[e] = s;
    g_tgt[e] = t;
    atomicAdd(&g_counts[t], 1);
}

// ---------------- K1: Q,K,V = x @ {Wq,Wk,Wv} --------------------------------
// block: 64 rows x 256 cols, 256 threads, 8x8 per thread, f32x2 packed FMA.
__global__ __launch_bounds__(256) void k_qkv(
    const float* __restrict__ x,
    const float* __restrict__ Wq, const float* __restrict__ Wk,
    const float* __restrict__ Wv)
{
    __shared__ __align__(16) float xs[64 * 128];   // 32 KB
    __shared__ __align__(16) float ws[8 * 256];    // 8 KB
    const int tid  = threadIdx.x;
    const int row0 = blockIdx.x * 64;

    for (int i = tid; i < 64 * 128; i += 256) {
        int r = i >> 7, c = i & 127;
        int gr = row0 + r;
        xs[i] = (gr < NN) ? x[gr * INC + c] : 0.0f;
    }
    __syncthreads();

    const int ty = tid >> 5;   // 0..7 : rows ty*8 .. +8
    const int tx = tid & 31;   // 0..31: cols tx*8 .. +8

    const float* Ws[3] = {Wq, Wk, Wv};
    float*       Os[3] = {g_Q, g_K, g_V};

    for (int m = 0; m < 3; m++) {
        const float* W = Ws[m];
        u64 acc[8][4];
        #pragma unroll
        for (int r = 0; r < 8; r++)
            #pragma unroll
            for (int j = 0; j < 4; j++) acc[r][j] = 0ull;

        for (int kt = 0; kt < 128; kt += 8) {
            __syncthreads();   // protect ws from previous tile readers
            for (int i = tid; i < 8 * 256; i += 256) {
                int kk = i >> 8, c = i & 255;
                ws[i] = W[(kt + kk) * OC + c];
            }
            __syncthreads();
            #pragma unroll
            for (int k = 0; k < 8; k++) {
                ulonglong2 b0 = *(const ulonglong2*)&ws[k * 256 + tx * 8];
                ulonglong2 b1 = *(const ulonglong2*)&ws[k * 256 + tx * 8 + 4];
                #pragma unroll
                for (int r = 0; r < 8; r++) {
                    u64 a = pack_dup(xs[(ty * 8 + r) * 128 + kt + k]);
                    fma2(acc[r][0], a, b0.x);
                    fma2(acc[r][1], a, b0.y);
                    fma2(acc[r][2], a, b1.x);
                    fma2(acc[r][3], a, b1.y);
                }
            }
        }
        float* O = Os[m];
        #pragma unroll
        for (int r = 0; r < 8; r++) {
            int gr = row0 + ty * 8 + r;
            if (gr < NN) {
                ulonglong2 o0; o0.x = acc[r][0]; o0.y = acc[r][1];
                ulonglong2 o1; o1.x = acc[r][2]; o1.y = acc[r][3];
                *(ulonglong2*)&O[(size_t)gr * OC + tx * 8]     = o0;
                *(ulonglong2*)&O[(size_t)gr * OC + tx * 8 + 4] = o1;
            }
        }
    }
}

// ---------------- K2: per-edge attention scores + per-head max --------------
// one warp per edge. lane l covers q/k float4 indices l (heads 0/1) and l+32
// (heads 2/3). 16-lane shfl reduction gives the 4 head dots.
__global__ __launch_bounds__(256) void k_scores(
    const float* __restrict__ ew,
    const float* __restrict__ We)
{
    __shared__ unsigned smax[HEADS];
    const int tid = threadIdx.x;
    if (tid < HEADS) smax[tid] = 0u;
    __syncthreads();

    const int warp = tid >> 5, lane = tid & 31;
    const int e = blockIdx.x * 8 + warp;
    if (e < NE) {
        int src = g_src[e];
        int tgt = g_tgt[e];
        const float4* q = (const float4*)(g_Q + (size_t)tgt * OC);
        const float4* k = (const float4*)(g_K + (size_t)src * OC);
        float4 qa = q[lane], qb = q[lane + 32];
        float4 ka = k[lane], kb = k[lane + 32];
        float d1 = qa.x * ka.x + qa.y * ka.y + qa.z * ka.z + qa.w * ka.w;
        float d2 = qb.x * kb.x + qb.y * kb.y + qb.z * kb.z + qb.w * kb.w;
        #pragma unroll
        for (int o = 8; o; o >>= 1) {
            d1 += __shfl_xor_sync(0xffffffffu, d1, o);
            d2 += __shfl_xor_sync(0xffffffffu, d2, o);
        }
        if ((lane & 15) == 0) {
            int hb = lane >> 4;            // 0 or 1
            float ewv = ew[e];
            float s1 = d1 * 0.125f + ewv * We[hb];        // head hb
            float s2 = d2 * 0.125f + ewv * We[hb + 2];    // head hb+2
            s1 = (s1 > 0.0f) ? s1 : 0.2f * s1;            // leaky_relu 0.2
            s2 = (s2 > 0.0f) ? s2 : 0.2f * s2;
            g_S[e * 4 + hb]     = s1;
            g_S[e * 4 + hb + 2] = s2;
            atomicMax(&smax[hb],     fflip(s1));
            atomicMax(&smax[hb + 2], fflip(s2));
        }
    }
    __syncthreads();
    if (tid < HEADS) atomicMax(&g_maxkey[tid], smax[tid]);
}

// ---------------- K3: p = exp(s - m), accumulate Z per head -----------------
__global__ __launch_bounds__(256) void k_exp() {
    float m0 = funflip(g_maxkey[0]), m1 = funflip(g_maxkey[1]);
    float m2 = funflip(g_maxkey[2]), m3 = funflip(g_maxkey[3]);
    float l0 = 0.f, l1 = 0.f, l2 = 0.f, l3 = 0.f;
    for (int e = blockIdx.x * blockDim.x + threadIdx.x; e < NE;
         e += gridDim.x * blockDim.x) {
        float4 s = *(const float4*)&g_S[e * 4];
        float4 p;
        p.x = __expf(s.x - m0);
        p.y = __expf(s.y - m1);
        p.z = __expf(s.z - m2);
        p.w = __expf(s.w - m3);
        *(float4*)&g_S[e * 4] = p;
        l0 += p.x; l1 += p.y; l2 += p.z; l3 += p.w;
    }
    #pragma unroll
    for (int o = 16; o; o >>= 1) {
        l0 += __shfl_xor_sync(0xffffffffu, l0, o);
        l1 += __shfl_xor_sync(0xffffffffu, l1, o);
        l2 += __shfl_xor_sync(0xffffffffu, l2, o);
        l3 += __shfl_xor_sync(0xffffffffu, l3, o);
    }
    __shared__ float part[8][HEADS];
    int warp = threadIdx.x >> 5, lane = threadIdx.x & 31;
    if (lane == 0) { part[warp][0] = l0; part[warp][1] = l1; part[warp][2] = l2; part[warp][3] = l3; }
    __syncthreads();
    if (threadIdx.x < HEADS) {
        float t = 0.f;
        #pragma unroll
        for (int w = 0; w < 8; w++) t += part[w][threadIdx.x];
        atomicAdd(&g_Z[threadIdx.x], t);
    }
}

// ---------------- K4a: exclusive prefix sum over counts (single block) ------
__global__ void k_scan() {
    __shared__ int tmp[1024];
    __shared__ int base;
    const int tid = threadIdx.x;
    if (tid == 0) { base = 0; g_offsets[0] = 0; }
    __syncthreads();
    for (int start = 0; start < NN; start += 1024) {
        int idx = start + tid;
        int v = (idx < NN) ? g_counts[idx] : 0;
        tmp[tid] = v;
        __syncthreads();
        for (int off = 1; off < 1024; off <<= 1) {
            int t = (tid >= off) ? tmp[tid - off] : 0;
            __syncthreads();
            tmp[tid] += t;
            __syncthreads();
        }
        if (idx < NN) g_offsets[idx + 1] = base + tmp[tid];
        __syncthreads();
        if (tid == 0) base += tmp[1023];
        __syncthreads();
    }
}

// ---------------- K4b: scatter edge ids into CSR order ----------------------
__global__ void k_scatter() {
    int e = blockIdx.x * blockDim.x + threadIdx.x;
    if (e < NE) {
        int tgt = g_tgt[e];
        int pos = g_offsets[tgt] + atomicAdd(&g_cursor[tgt], 1);
        g_order[pos] = e;
    }
}

// ---------------- K5: per-target-node gather-aggregate ----------------------
// one warp per node; lane l accumulates cols [4l,4l+4) (heads 0/1) and
// [128+4l, ...) (heads 2/3). single clean row write, no float atomics.
__global__ __launch_bounds__(256) void k_agg() {
    const int warp = threadIdx.x >> 5, lane = threadIdx.x & 31;
    const int n = blockIdx.x * 8 + warp;
    if (n >= NN) return;
    const int h1 = lane >> 4;          // 0/1
    const float iz1 = 1.0f / g_Z[h1];
    const float iz2 = 1.0f / g_Z[h1 + 2];
    float4 a1 = make_float4(0.f, 0.f, 0.f, 0.f);
    float4 a2 = make_float4(0.f, 0.f, 0.f, 0.f);
    const int beg = g_offsets[n], end = g_offsets[n + 1];
    for (int j = beg; j < end; j++) {
        int e = g_order[j];
        int src = g_src[e];
        float4 p = *(const float4*)&g_S[e * 4];
        float w1 = (lane < 16) ? p.x : p.y;   // heads 0/1
        float w2 = (lane < 16) ? p.z : p.w;   // heads 2/3
        const float4* v = (const float4*)(g_V + (size_t)src * OC);
        float4 v1 = v[lane], v2 = v[lane + 32];
        a1.x += w1 * v1.x; a1.y += w1 * v1.y; a1.z += w1 * v1.z; a1.w += w1 * v1.w;
        a2.x += w2 * v2.x; a2.y += w2 * v2.y; a2.z += w2 * v2.z; a2.w += w2 * v2.w;
    }
    a1.x *= iz1; a1.y *= iz1; a1.z *= iz1; a1.w *= iz1;
    a2.x *= iz2; a2.y *= iz2; a2.z *= iz2; a2.w *= iz2;
    float* o = g_agg + (size_t)n * OC;
    ((float4*)o)[lane]      = a1;
    ((float4*)o)[lane + 32] = a2;
}

// ---------------- K6: out = agg @ Wout + b_out ------------------------------
// block: 128 rows x 64 cols, 256 threads, 4x8 per thread, f32x2 packed FMA.
#define ASW 33
__global__ __launch_bounds__(256) void k_out(
    const float* __restrict__ Wout, const float* __restrict__ bout,
    float* __restrict__ out)
{
    __shared__ __align__(16) float as[128 * ASW];  // ~16.5 KB (padded)
    __shared__ __align__(16) float ws[32 * 64];    // 8 KB
    const int tid  = threadIdx.x;
    const int row0 = blockIdx.x * 128;
    const int ty = tid >> 3;   // 0..31 : rows ty*4..+4
    const int tx = tid & 7;    // 0..7  : cols tx*8..+8

    u64 acc[4][4];
    #pragma unroll
    for (int r = 0; r < 4; r++)
        #pragma unroll
        for (int j = 0; j < 4; j++) acc[r][j] = 0ull;

    for (int kt = 0; kt < OC; kt += 32) {
        __syncthreads();
        for (int i = tid; i < 128 * 32; i += 256) {
            int r = i >> 5, c = i & 31;
            int gr = row0 + r;
            as[r * ASW + c] = (gr < NN) ? g_agg[(size_t)gr * OC + kt + c] : 0.0f;
        }
        for (int i = tid; i < 32 * 64; i += 256) {
            int r = i >> 6, c = i & 63;
            ws[i] = Wout[(kt + r) * OUTC + c];
        }
        __syncthreads();
        #pragma unroll
        for (int k = 0; k < 32; k++) {
            ulonglong2 b0 = *(const ulonglong2*)&ws[k * 64 + tx * 8];
            ulonglong2 b1 = *(const ulonglong2*)&ws[k * 64 + tx * 8 + 4];
            #pragma unroll
            for (int r = 0; r < 4; r++) {
                u64 a = pack_dup(as[(ty * 4 + r) * ASW + k]);
                fma2(acc[r][0], a, b0.x);
                fma2(acc[r][1], a, b0.y);
                fma2(acc[r][2], a, b1.x);
                fma2(acc[r][3], a, b1.y);
            }
        }
    }

    float4 bb0 = *(const float4*)&bout[tx * 8];
    float4 bb1 = *(const float4*)&bout[tx * 8 + 4];
    #pragma unroll
    for (int r = 0; r < 4; r++) {
        int gr = row0 + ty * 4 + r;
        if (gr < NN) {
            float2 f0 = unpack2(acc[r][0]), f1 = unpack2(acc[r][1]);
            float2 f2 = unpack2(acc[r][2]), f3 = unpack2(acc[r][3]);
            float4 o0 = make_float4(f0.x + bb0.x, f0.y + bb0.y, f1.x + bb0.z, f1.y + bb0.w);
            float4 o1 = make_float4(f2.x + bb1.x, f2.y + bb1.y, f3.x + bb1.z, f3.y + bb1.w);
            *(float4*)&out[(size_t)gr * OUTC + tx * 8]     = o0;
            *(float4*)&out[(size_t)gr * OUTC + tx * 8 + 4] = o1;
        }
    }
}

// ---------------- launch -----------------------------------------------------
extern "C" void kernel_launch(void* const* d_in, const int* in_sizes, int n_in,
                              void* d_out, int out_size)
{
    const float* x    = (const float*)d_in[0];
    const void*  ei   = d_in[1];                 // int32 or int64 [2, E] (probed)
    const float* ew   = (const float*)d_in[2];
    const float* Wq   = (const float*)d_in[3];
    const float* Wk   = (const float*)d_in[4];
    const float* Wv   = (const float*)d_in[5];
    const float* We   = (const float*)d_in[6];
    const float* Wout = (const float*)d_in[7];
    const float* bout = (const float*)d_in[8];
    float*       out  = (float*)d_out;

    k_init   <<<(NN + 255) / 256, 256>>>(ei);
    k_decode <<<(NE + 255) / 256, 256>>>(ei);
    k_qkv    <<<(NN + 63) / 64,   256>>>(x, Wq, Wk, Wv);
    k_scores <<<NE / 8,           256>>>(ew, We);
    k_exp    <<<512,              256>>>();
    k_scan   <<<1,               1024>>>();
    k_scatter<<<(NE + 255) / 256, 256>>>();
    k_agg    <<<(NN + 7) / 8,     256>>>();
    k_out    <<<(NN + 127) / 128, 256>>>(Wout, bout, out);
}

// round 9
// speedup vs baseline: 1.1189x; 1.1189x over previous
#include <cuda_runtime.h>

#define NN 50000
#define NE 500000
#define INC 128
#define OC 256      // OUT_CH * HEADS
#define HEADS 4
#define OUTC 64
#define NBLK 49     // ceil(NN/1024)

typedef unsigned long long u64;

// ---------------- scratch (static device globals; no runtime allocation) ----
__device__ __align__(16) float g_Q[NN * OC];
__device__ __align__(16) float g_K[NN * OC];
__device__ __align__(16) float g_V[NN * OC];
__device__ __align__(16) float g_S[NE * HEADS];   // CSR-ordered scores -> exp
__device__ __align__(16) float g_agg[NN * OC];
__device__ int   g_src[NE];          // edge-ordered
__device__ int   g_tgt[NE];
__device__ int   g_csr_src[NE];      // CSR-ordered (by target)
__device__ int   g_csr_tgt[NE];
__device__ float g_csr_ew[NE];
__device__ int   g_counts[NN];       // histogram, then scatter cursor
__device__ int   g_offsets[NN + 1];
__device__ int   g_bsum[NBLK];
__device__ int   g_bbase[NBLK];
__device__ unsigned g_maxkey[HEADS];
__device__ float g_Z[HEADS];
__device__ int   g_is64;

// ---------------- helpers ---------------------------------------------------
__device__ __forceinline__ u64 pack_dup(float v) {
    u64 r; asm("mov.b64 %0, {%1,%1};" : "=l"(r) : "f"(v)); return r;
}
__device__ __forceinline__ void fma2(u64 &d, u64 a, u64 b) {
    asm("fma.rn.f32x2 %0, %1, %2, %3;" : "=l"(d) : "l"(a), "l"(b), "l"(d));
}
__device__ __forceinline__ float2 unpack2(u64 v) {
    float2 f; asm("mov.b64 {%0,%1}, %2;" : "=f"(f.x), "=f"(f.y) : "l"(v)); return f;
}
__device__ __forceinline__ unsigned fflip(float f) {
    unsigned u = __float_as_uint(f);
    return u ^ ((u >> 31) ? 0xFFFFFFFFu : 0x80000000u);
}
__device__ __forceinline__ float funflip(unsigned u) {
    return __uint_as_float(u ^ ((u >> 31) ? 0x80000000u : 0xFFFFFFFFu));
}

// ---------------- K0: init + edge-index dtype probe -------------------------
__global__ void k_init(const void* ei) {
    int i = blockIdx.x * blockDim.x + threadIdx.x;
    if (i < NN) g_counts[i] = 0;
    if (i < HEADS) { g_maxkey[i] = 0u; g_Z[i] = 0.0f; }
    if (i == 0) {
        // int64 layout -> first 64 int64 values all in [0, NN).
        // int32 layout -> an int64 read fuses two random ids, ~surely >= 2^32.
        const long long* p = (const long long*)ei;
        int ok = 1;
        for (int j = 0; j < 64; j++) {
            long long v = p[j];
            if (v < 0 || v >= NN) { ok = 0; break; }
        }
        g_is64 = ok;
    }
}

// ---------------- K0b: decode edge index to int32 + target histogram --------
__global__ void k_decode(const void* ei) {
    int e = blockIdx.x * blockDim.x + threadIdx.x;
    if (e >= NE) return;
    int s, t;
    if (g_is64) {
        const long long* p = (const long long*)ei;
        s = (int)p[e];
        t = (int)p[NE + e];
    } else {
        const int* p = (const int*)ei;
        s = p[e];
        t = p[NE + e];
    }
    g_src[e] = s;
    g_tgt[e] = t;
    atomicAdd(&g_counts[t], 1);
}

// ---------------- K1: Q,K,V = x @ {Wq,Wk,Wv} --------------------------------
// block: 64 rows x 256 cols, 256 threads, 8x8 per thread, f32x2 packed FMA.
__global__ __launch_bounds__(256) void k_qkv(
    const float* __restrict__ x,
    const float* __restrict__ Wq, const float* __restrict__ Wk,
    const float* __restrict__ Wv)
{
    __shared__ __align__(16) float xs[64 * 128];   // 32 KB
    __shared__ __align__(16) float ws[8 * 256];    // 8 KB
    const int tid  = threadIdx.x;
    const int row0 = blockIdx.x * 64;

    for (int i = tid; i < 64 * 128; i += 256) {
        int r = i >> 7, c = i & 127;
        int gr = row0 + r;
        xs[i] = (gr < NN) ? x[gr * INC + c] : 0.0f;
    }
    __syncthreads();

    const int ty = tid >> 5;   // 0..7 : rows ty*8 .. +8
    const int tx = tid & 31;   // 0..31: cols tx*8 .. +8

    const float* Ws[3] = {Wq, Wk, Wv};
    float*       Os[3] = {g_Q, g_K, g_V};

    for (int m = 0; m < 3; m++) {
        const float* W = Ws[m];
        u64 acc[8][4];
        #pragma unroll
        for (int r = 0; r < 8; r++)
            #pragma unroll
            for (int j = 0; j < 4; j++) acc[r][j] = 0ull;

        for (int kt = 0; kt < 128; kt += 8) {
            __syncthreads();   // protect ws from previous tile readers
            for (int i = tid; i < 8 * 256; i += 256) {
                int kk = i >> 8, c = i & 255;
                ws[i] = W[(kt + kk) * OC + c];
            }
            __syncthreads();
            #pragma unroll
            for (int k = 0; k < 8; k++) {
                ulonglong2 b0 = *(const ulonglong2*)&ws[k * 256 + tx * 8];
                ulonglong2 b1 = *(const ulonglong2*)&ws[k * 256 + tx * 8 + 4];
                #pragma unroll
                for (int r = 0; r < 8; r++) {
                    u64 a = pack_dup(xs[(ty * 8 + r) * 128 + kt + k]);
                    fma2(acc[r][0], a, b0.x);
                    fma2(acc[r][1], a, b0.y);
                    fma2(acc[r][2], a, b1.x);
                    fma2(acc[r][3], a, b1.y);
                }
            }
        }
        float* O = Os[m];
        #pragma unroll
        for (int r = 0; r < 8; r++) {
            int gr = row0 + ty * 8 + r;
            if (gr < NN) {
                ulonglong2 o0; o0.x = acc[r][0]; o0.y = acc[r][1];
                ulonglong2 o1; o1.x = acc[r][2]; o1.y = acc[r][3];
                *(ulonglong2*)&O[(size_t)gr * OC + tx * 8]     = o0;
                *(ulonglong2*)&O[(size_t)gr * OC + tx * 8 + 4] = o1;
            }
        }
    }
}

// ---------------- K2a/b/c: hierarchical exclusive scan of counts ------------
__global__ __launch_bounds__(1024) void k_scan1() {
    __shared__ int wsum[32];
    const int tid = threadIdx.x, lane = tid & 31, warp = tid >> 5;
    int idx = blockIdx.x * 1024 + tid;
    int v = (idx < NN) ? g_counts[idx] : 0;
    int xv = v;
    #pragma unroll
    for (int o = 1; o < 32; o <<= 1) {
        int t = __shfl_up_sync(0xffffffffu, xv, o);
        if (lane >= o) xv += t;
    }
    if (lane == 31) wsum[warp] = xv;
    __syncthreads();
    if (warp == 0) {
        int s = wsum[lane];
        #pragma unroll
        for (int o = 1; o < 32; o <<= 1) {
            int t = __shfl_up_sync(0xffffffffu, s, o);
            if (lane >= o) s += t;
        }
        wsum[lane] = s;
    }
    __syncthreads();
    int incl = xv + (warp ? wsum[warp - 1] : 0);
    if (idx < NN) g_offsets[idx + 1] = incl;          // block-local inclusive
    if (tid == 1023) g_bsum[blockIdx.x] = incl;       // block total
}
__global__ void k_scan2() {
    // tiny: exclusive scan of 49 block sums, single thread
    int run = 0;
    for (int b = 0; b < NBLK; b++) { g_bbase[b] = run; run += g_bsum[b]; }
    g_offsets[0] = 0;
}
__global__ __launch_bounds__(1024) void k_scan3() {
    int idx = blockIdx.x * 1024 + threadIdx.x;
    int base = g_bbase[blockIdx.x];
    if (idx < NN) {
        g_offsets[idx + 1] += base;
        g_counts[idx] = 0;            // re-zero: becomes scatter cursor
    }
}

// ---------------- K3: scatter edge data into CSR (by target) order ----------
__global__ void k_scatter(const float* __restrict__ ew) {
    int e = blockIdx.x * blockDim.x + threadIdx.x;
    if (e < NE) {
        int t = g_tgt[e];
        int pos = g_offsets[t] + atomicAdd(&g_counts[t], 1);
        g_csr_src[pos] = g_src[e];
        g_csr_tgt[pos] = t;
        g_csr_ew[pos]  = ew[e];
    }
}

// ---------------- K4: attention scores in CSR order + per-head max ----------
// one warp per CSR position. Consecutive positions share the same target ->
// the Q row stays in L1 (avg degree ~10 => ~10x less Q traffic).
__global__ __launch_bounds__(256) void k_scores(const float* __restrict__ We)
{
    __shared__ unsigned smax[HEADS];
    const int tid = threadIdx.x;
    if (tid < HEADS) smax[tid] = 0u;
    __syncthreads();

    const int warp = tid >> 5, lane = tid & 31;
    const int p = blockIdx.x * 8 + warp;
    if (p < NE) {
        int src = g_csr_src[p];
        int tgt = g_csr_tgt[p];
        const float4* q = (const float4*)(g_Q + (size_t)tgt * OC);
        const float4* k = (const float4*)(g_K + (size_t)src * OC);
        float4 qa = q[lane], qb = q[lane + 32];
        float4 ka = k[lane], kb = k[lane + 32];
        float d1 = qa.x * ka.x + qa.y * ka.y + qa.z * ka.z + qa.w * ka.w;
        float d2 = qb.x * kb.x + qb.y * kb.y + qb.z * kb.z + qb.w * kb.w;
        #pragma unroll
        for (int o = 8; o; o >>= 1) {
            d1 += __shfl_xor_sync(0xffffffffu, d1, o);
            d2 += __shfl_xor_sync(0xffffffffu, d2, o);
        }
        if ((lane & 15) == 0) {
            int hb = lane >> 4;            // 0 or 1
            float ewv = g_csr_ew[p];
            float s1 = d1 * 0.125f + ewv * We[hb];        // head hb
            float s2 = d2 * 0.125f + ewv * We[hb + 2];    // head hb+2
            s1 = (s1 > 0.0f) ? s1 : 0.2f * s1;            // leaky_relu 0.2
            s2 = (s2 > 0.0f) ? s2 : 0.2f * s2;
            g_S[p * 4 + hb]     = s1;
            g_S[p * 4 + hb + 2] = s2;
            atomicMax(&smax[hb],     fflip(s1));
            atomicMax(&smax[hb + 2], fflip(s2));
        }
    }
    __syncthreads();
    if (tid < HEADS) atomicMax(&g_maxkey[tid], smax[tid]);
}

// ---------------- K5: p = exp(s - m), accumulate Z per head -----------------
__global__ __launch_bounds__(256) void k_exp() {
    float m0 = funflip(g_maxkey[0]), m1 = funflip(g_maxkey[1]);
    float m2 = funflip(g_maxkey[2]), m3 = funflip(g_maxkey[3]);
    float l0 = 0.f, l1 = 0.f, l2 = 0.f, l3 = 0.f;
    for (int e = blockIdx.x * blockDim.x + threadIdx.x; e < NE;
         e += gridDim.x * blockDim.x) {
        float4 s = *(const float4*)&g_S[e * 4];
        float4 p;
        p.x = __expf(s.x - m0);
        p.y = __expf(s.y - m1);
        p.z = __expf(s.z - m2);
        p.w = __expf(s.w - m3);
        *(float4*)&g_S[e * 4] = p;
        l0 += p.x; l1 += p.y; l2 += p.z; l3 += p.w;
    }
    #pragma unroll
    for (int o = 16; o; o >>= 1) {
        l0 += __shfl_xor_sync(0xffffffffu, l0, o);
        l1 += __shfl_xor_sync(0xffffffffu, l1, o);
        l2 += __shfl_xor_sync(0xffffffffu, l2, o);
        l3 += __shfl_xor_sync(0xffffffffu, l3, o);
    }
    __shared__ float part[8][HEADS];
    int warp = threadIdx.x >> 5, lane = threadIdx.x & 31;
    if (lane == 0) { part[warp][0] = l0; part[warp][1] = l1; part[warp][2] = l2; part[warp][3] = l3; }
    __syncthreads();
    if (threadIdx.x < HEADS) {
        float t = 0.f;
        #pragma unroll
        for (int w = 0; w < 8; w++) t += part[w][threadIdx.x];
        atomicAdd(&g_Z[threadIdx.x], t);
    }
}

// ---------------- K6: per-target-node gather-aggregate ----------------------
// one warp per node; streams contiguous csr_src / S, random V row gathers
// unrolled x4 for memory-level parallelism. No float atomics.
__global__ __launch_bounds__(256) void k_agg() {
    const int warp = threadIdx.x >> 5, lane = threadIdx.x & 31;
    const int n = blockIdx.x * 8 + warp;
    if (n >= NN) return;
    const int h1 = lane >> 4;          // 0/1
    const float iz1 = 1.0f / g_Z[h1];
    const float iz2 = 1.0f / g_Z[h1 + 2];
    float4 a1 = make_float4(0.f, 0.f, 0.f, 0.f);
    float4 a2 = make_float4(0.f, 0.f, 0.f, 0.f);
    const int beg = g_offsets[n], end = g_offsets[n + 1];
    const float4* S4 = (const float4*)g_S;
    int j = beg;
    for (; j + 4 <= end; j += 4) {
        int s0 = g_csr_src[j],     s1 = g_csr_src[j + 1];
        int s2 = g_csr_src[j + 2], s3 = g_csr_src[j + 3];
        float4 p0 = S4[j],     p1 = S4[j + 1];
        float4 p2 = S4[j + 2], p3 = S4[j + 3];
        const float4* v0 = (const float4*)(g_V + (size_t)s0 * OC);
        const float4* v1 = (const float4*)(g_V + (size_t)s1 * OC);
        const float4* v2 = (const float4*)(g_V + (size_t)s2 * OC);
        const float4* v3 = (const float4*)(g_V + (size_t)s3 * OC);
        float4 va0 = v0[lane], vb0 = v0[lane + 32];
        float4 va1 = v1[lane], vb1 = v1[lane + 32];
        float4 va2 = v2[lane], vb2 = v2[lane + 32];
        float4 va3 = v3[lane], vb3 = v3[lane + 32];
        float w10 = (lane < 16) ? p0.x : p0.y, w20 = (lane < 16) ? p0.z : p0.w;
        float w11 = (lane < 16) ? p1.x : p1.y, w21 = (lane < 16) ? p1.z : p1.w;
        float w12 = (lane < 16) ? p2.x : p2.y, w22 = (lane < 16) ? p2.z : p2.w;
        float w13 = (lane < 16) ? p3.x : p3.y, w23 = (lane < 16) ? p3.z : p3.w;
        a1.x += w10 * va0.x; a1.y += w10 * va0.y; a1.z += w10 * va0.z; a1.w += w10 * va0.w;
        a2.x += w20 * vb0.x; a2.y += w20 * vb0.y; a2.z += w20 * vb0.z; a2.w += w20 * vb0.w;
        a1.x += w11 * va1.x; a1.y += w11 * va1.y; a1.z += w11 * va1.z; a1.w += w11 * va1.w;
        a2.x += w21 * vb1.x; a2.y += w21 * vb1.y; a2.z += w21 * vb1.z; a2.w += w21 * vb1.w;
        a1.x += w12 * va2.x; a1.y += w12 * va2.y; a1.z += w12 * va2.z; a1.w += w12 * va2.w;
        a2.x += w22 * vb2.x; a2.y += w22 * vb2.y; a2.z += w22 * vb2.z; a2.w += w22 * vb2.w;
        a1.x += w13 * va3.x; a1.y += w13 * va3.y; a1.z += w13 * va3.z; a1.w += w13 * va3.w;
        a2.x += w23 * vb3.x; a2.y += w23 * vb3.y; a2.z += w23 * vb3.z; a2.w += w23 * vb3.w;
    }
    for (; j < end; j++) {
        int s0 = g_csr_src[j];
        float4 p0 = S4[j];
        const float4* v0 = (const float4*)(g_V + (size_t)s0 * OC);
        float4 va0 = v0[lane], vb0 = v0[lane + 32];
        float w10 = (lane < 16) ? p0.x : p0.y;
        float w20 = (lane < 16) ? p0.z : p0.w;
        a1.x += w10 * va0.x; a1.y += w10 * va0.y; a1.z += w10 * va0.z; a1.w += w10 * va0.w;
        a2.x += w20 * vb0.x; a2.y += w20 * vb0.y; a2.z += w20 * vb0.z; a2.w += w20 * vb0.w;
    }
    a1.x *= iz1; a1.y *= iz1; a1.z *= iz1; a1.w *= iz1;
    a2.x *= iz2; a2.y *= iz2; a2.z *= iz2; a2.w *= iz2;
    float* o = g_agg + (size_t)n * OC;
    ((float4*)o)[lane]      = a1;
    ((float4*)o)[lane + 32] = a2;
}

// ---------------- K7: out = agg @ Wout + b_out ------------------------------
// block: 128 rows x 64 cols, 256 threads, 4x8 per thread, f32x2 packed FMA.
#define ASW 33
__global__ __launch_bounds__(256) void k_out(
    const float* __restrict__ Wout, const float* __restrict__ bout,
    float* __restrict__ out)
{
    __shared__ __align__(16) float as[128 * ASW];  // ~16.5 KB (padded)
    __shared__ __align__(16) float ws[32 * 64];    // 8 KB
    const int tid  = threadIdx.x;
    const int row0 = blockIdx.x * 128;
    const int ty = tid >> 3;   // 0..31 : rows ty*4..+4
    const int tx = tid & 7;    // 0..7  : cols tx*8..+8

    u64 acc[4][4];
    #pragma unroll
    for (int r = 0; r < 4; r++)
        #pragma unroll
        for (int j = 0; j < 4; j++) acc[r][j] = 0ull;

    for (int kt = 0; kt < OC; kt += 32) {
        __syncthreads();
        for (int i = tid; i < 128 * 32; i += 256) {
            int r = i >> 5, c = i & 31;
            int gr = row0 + r;
            as[r * ASW + c] = (gr < NN) ? g_agg[(size_t)gr * OC + kt + c] : 0.0f;
        }
        for (int i = tid; i < 32 * 64; i += 256) {
            int r = i >> 6, c = i & 63;
            ws[i] = Wout[(kt + r) * OUTC + c];
        }
        __syncthreads();
        #pragma unroll
        for (int k = 0; k < 32; k++) {
            ulonglong2 b0 = *(const ulonglong2*)&ws[k * 64 + tx * 8];
            ulonglong2 b1 = *(const ulonglong2*)&ws[k * 64 + tx * 8 + 4];
            #pragma unroll
            for (int r = 0; r < 4; r++) {
                u64 a = pack_dup(as[(ty * 4 + r) * ASW + k]);
                fma2(acc[r][0], a, b0.x);
                fma2(acc[r][1], a, b0.y);
                fma2(acc[r][2], a, b1.x);
                fma2(acc[r][3], a, b1.y);
            }
        }
    }

    float4 bb0 = *(const float4*)&bout[tx * 8];
    float4 bb1 = *(const float4*)&bout[tx * 8 + 4];
    #pragma unroll
    for (int r = 0; r < 4; r++) {
        int gr = row0 + ty * 4 + r;
        if (gr < NN) {
            float2 f0 = unpack2(acc[r][0]), f1 = unpack2(acc[r][1]);
            float2 f2 = unpack2(acc[r][2]), f3 = unpack2(acc[r][3]);
            float4 o0 = make_float4(f0.x + bb0.x, f0.y + bb0.y, f1.x + bb0.z, f1.y + bb0.w);
            float4 o1 = make_float4(f2.x + bb1.x, f2.y + bb1.y, f3.x + bb1.z, f3.y + bb1.w);
            *(float4*)&out[(size_t)gr * OUTC + tx * 8]     = o0;
            *(float4*)&out[(size_t)gr * OUTC + tx * 8 + 4] = o1;
        }
    }
}

// ---------------- launch -----------------------------------------------------
extern "C" void kernel_launch(void* const* d_in, const int* in_sizes, int n_in,
                              void* d_out, int out_size)
{
    const float* x    = (const float*)d_in[0];
    const void*  ei   = d_in[1];                 // int32 or int64 [2, E] (probed)
    const float* ew   = (const float*)d_in[2];
    const float* Wq   = (const float*)d_in[3];
    const float* Wk   = (const float*)d_in[4];
    const float* Wv   = (const float*)d_in[5];
    const float* We   = (const float*)d_in[6];
    const float* Wout = (const float*)d_in[7];
    const float* bout = (const float*)d_in[8];
    float*       out  = (float*)d_out;

    k_init   <<<(NN + 255) / 256, 256>>>(ei);
    k_decode <<<(NE + 255) / 256, 256>>>(ei);
    k_qkv    <<<(NN + 63) / 64,   256>>>(x, Wq, Wk, Wv);
    k_scan1  <<<NBLK,            1024>>>();
    k_scan2  <<<1,                  1>>>();
    k_scan3  <<<NBLK,            1024>>>();
    k_scatter<<<(NE + 255) / 256, 256>>>(ew);
    k_scores <<<NE / 8,           256>>>(We);
    k_exp    <<<512,              256>>>();
    k_agg    <<<(NN + 7) / 8,     256>>>();
    k_out    <<<(NN + 127) / 128, 256>>>(Wout, bout, out);
}

// round 10
// speedup vs baseline: 1.4803x; 1.3231x over previous
#include <cuda_runtime.h>

#define NN 50000
#define NE 500000
#define INC 128
#define OC 256      // OUT_CH * HEADS
#define HEADS 4
#define OUTC 64
#define NBLK 49     // ceil(NN/1024)

typedef unsigned long long u64;

// ---------------- scratch (static device globals; no runtime allocation) ----
__device__ __align__(16) float g_Q[NN * OC];
__device__ __align__(16) float g_K[NN * OC];
__device__ __align__(16) float g_V[NN * OC];
__device__ __align__(16) float g_S[NE * HEADS];   // CSR-ordered scores -> exp
__device__ __align__(16) float g_agg[NN * OC];
__device__ int   g_src[NE];          // edge-ordered
__device__ int   g_tgt[NE];
__device__ int   g_csr_src[NE];      // CSR-ordered (by target)
__device__ int   g_csr_tgt[NE];
__device__ float g_csr_ew[NE];
__device__ int   g_counts[NN];       // histogram, then scatter cursor
__device__ int   g_offsets[NN + 1];
__device__ int   g_bsum[NBLK];
__device__ int   g_bbase[NBLK];
__device__ unsigned g_maxkey[HEADS];
__device__ float g_Z[HEADS];
__device__ int   g_is64;

// ---------------- helpers ---------------------------------------------------
__device__ __forceinline__ u64 pack_dup(float v) {
    u64 r; asm("mov.b64 %0, {%1,%1};" : "=l"(r) : "f"(v)); return r;
}
__device__ __forceinline__ void fma2(u64 &d, u64 a, u64 b) {
    asm("fma.rn.f32x2 %0, %1, %2, %3;" : "=l"(d) : "l"(a), "l"(b), "l"(d));
}
__device__ __forceinline__ float2 unpack2(u64 v) {
    float2 f; asm("mov.b64 {%0,%1}, %2;" : "=f"(f.x), "=f"(f.y) : "l"(v)); return f;
}
__device__ __forceinline__ unsigned fflip(float f) {
    unsigned u = __float_as_uint(f);
    return u ^ ((u >> 31) ? 0xFFFFFFFFu : 0x80000000u);
}
__device__ __forceinline__ float funflip(unsigned u) {
    return __uint_as_float(u ^ ((u >> 31) ? 0x80000000u : 0xFFFFFFFFu));
}

// ---------------- K0: init + edge-index dtype probe -------------------------
__global__ void k_init(const void* ei) {
    int i = blockIdx.x * blockDim.x + threadIdx.x;
    if (i < NN) g_counts[i] = 0;
    if (i < HEADS) { g_maxkey[i] = 0u; g_Z[i] = 0.0f; }
    if (i == 0) {
        // int64 layout -> first 64 int64 values all in [0, NN).
        // int32 layout -> an int64 read fuses two random ids, ~surely >= 2^32.
        const long long* p = (const long long*)ei;
        int ok = 1;
        for (int j = 0; j < 64; j++) {
            long long v = p[j];
            if (v < 0 || v >= NN) { ok = 0; break; }
        }
        g_is64 = ok;
    }
}

// ---------------- K0b: decode edge index to int32 + target histogram --------
__global__ void k_decode(const void* ei) {
    int e = blockIdx.x * blockDim.x + threadIdx.x;
    if (e >= NE) return;
    int s, t;
    if (g_is64) {
        const long long* p = (const long long*)ei;
        s = (int)p[e];
        t = (int)p[NE + e];
    } else {
        const int* p = (const int*)ei;
        s = p[e];
        t = p[NE + e];
    }
    g_src[e] = s;
    g_tgt[e] = t;
    atomicAdd(&g_counts[t], 1);
}

// ---------------- K1: Q,K,V = x @ {Wq,Wk,Wv} --------------------------------
// block: 64 rows x 256 cols, 256 threads, 8x8 per thread, f32x2 packed FMA.
// Double-buffered W tiles (1 sync/tile); conflict-free 16B-stride b reads:
// thread covers cols [tx*4, tx*4+4) and [128+tx*4, 128+tx*4+4).
__global__ __launch_bounds__(256) void k_qkv(
    const float* __restrict__ x,
    const float* __restrict__ Wq, const float* __restrict__ Wk,
    const float* __restrict__ Wv)
{
    __shared__ __align__(16) float xs[64 * 128];     // 32 KB
    __shared__ __align__(16) float ws[2][8 * 256];   // 16 KB (double buffer)
    const int tid  = threadIdx.x;
    const int row0 = blockIdx.x * 64;

    for (int i = tid; i < 64 * 128; i += 256) {
        int r = i >> 7, c = i & 127;
        int gr = row0 + r;
        xs[i] = (gr < NN) ? x[gr * INC + c] : 0.0f;
    }

    const int ty = tid >> 5;   // 0..7 : rows ty*8 .. +8
    const int tx = tid & 31;   // 0..31: cols tx*4 and 128+tx*4

    const float* Ws[3] = {Wq, Wk, Wv};
    float*       Os[3] = {g_Q, g_K, g_V};

    for (int m = 0; m < 3; m++) {
        const float* W = Ws[m];
        // stage tile 0 into buffer 0
        for (int i = tid; i < 8 * 256; i += 256)
            ws[0][i] = W[(i >> 8) * OC + (i & 255)];
        __syncthreads();   // also covers the xs fill on m==0

        u64 acc[8][4];
        #pragma unroll
        for (int r = 0; r < 8; r++)
            #pragma unroll
            for (int j = 0; j < 4; j++) acc[r][j] = 0ull;

        for (int t = 0; t < 16; t++) {
            const int cur = t & 1;
            if (t + 1 < 16) {
                const int kt1 = (t + 1) * 8;
                for (int i = tid; i < 8 * 256; i += 256)
                    ws[cur ^ 1][i] = W[(kt1 + (i >> 8)) * OC + (i & 255)];
            }
            const int kt = t * 8;
            #pragma unroll
            for (int k = 0; k < 8; k++) {
                ulonglong2 b0 = *(const ulonglong2*)&ws[cur][k * 256 + tx * 4];
                ulonglong2 b1 = *(const ulonglong2*)&ws[cur][k * 256 + 128 + tx * 4];
                #pragma unroll
                for (int r = 0; r < 8; r++) {
                    u64 a = pack_dup(xs[(ty * 8 + r) * 128 + kt + k]);
                    fma2(acc[r][0], a, b0.x);
                    fma2(acc[r][1], a, b0.y);
                    fma2(acc[r][2], a, b1.x);
                    fma2(acc[r][3], a, b1.y);
                }
            }
            __syncthreads();   // readers of ws[cur] done; ws[cur^1] staged
        }
        float* O = Os[m];
        #pragma unroll
        for (int r = 0; r < 8; r++) {
            int gr = row0 + ty * 8 + r;
            if (gr < NN) {
                float2 f0 = unpack2(acc[r][0]), f1 = unpack2(acc[r][1]);
                float2 f2 = unpack2(acc[r][2]), f3 = unpack2(acc[r][3]);
                float4 o0 = make_float4(f0.x, f0.y, f1.x, f1.y);
                float4 o1 = make_float4(f2.x, f2.y, f3.x, f3.y);
                *(float4*)&O[(size_t)gr * OC + tx * 4]       = o0;
                *(float4*)&O[(size_t)gr * OC + 128 + tx * 4] = o1;
            }
        }
    }
}

// ---------------- K2a/b/c: hierarchical exclusive scan of counts ------------
__global__ __launch_bounds__(1024) void k_scan1() {
    __shared__ int wsum[32];
    const int tid = threadIdx.x, lane = tid & 31, warp = tid >> 5;
    int idx = blockIdx.x * 1024 + tid;
    int v = (idx < NN) ? g_counts[idx] : 0;
    int xv = v;
    #pragma unroll
    for (int o = 1; o < 32; o <<= 1) {
        int t = __shfl_up_sync(0xffffffffu, xv, o);
        if (lane >= o) xv += t;
    }
    if (lane == 31) wsum[warp] = xv;
    __syncthreads();
    if (warp == 0) {
        int s = wsum[lane];
        #pragma unroll
        for (int o = 1; o < 32; o <<= 1) {
            int t = __shfl_up_sync(0xffffffffu, s, o);
            if (lane >= o) s += t;
        }
        wsum[lane] = s;
    }
    __syncthreads();
    int incl = xv + (warp ? wsum[warp - 1] : 0);
    if (idx < NN) g_offsets[idx + 1] = incl;          // block-local inclusive
    if (tid == 1023) g_bsum[blockIdx.x] = incl;       // block total
}
__global__ void k_scan2() {
    // tiny: exclusive scan of 49 block sums, single thread
    int run = 0;
    for (int b = 0; b < NBLK; b++) { g_bbase[b] = run; run += g_bsum[b]; }
    g_offsets[0] = 0;
}
__global__ __launch_bounds__(1024) void k_scan3() {
    int idx = blockIdx.x * 1024 + threadIdx.x;
    int base = g_bbase[blockIdx.x];
    if (idx < NN) {
        g_offsets[idx + 1] += base;
        g_counts[idx] = 0;            // re-zero: becomes scatter cursor
    }
}

// ---------------- K3: scatter edge data into CSR (by target) order ----------
__global__ void k_scatter(const float* __restrict__ ew) {
    int e = blockIdx.x * blockDim.x + threadIdx.x;
    if (e < NE) {
        int t = g_tgt[e];
        int pos = g_offsets[t] + atomicAdd(&g_counts[t], 1);
        g_csr_src[pos] = g_src[e];
        g_csr_tgt[pos] = t;
        g_csr_ew[pos]  = ew[e];
    }
}

// ---------------- K4: attention scores in CSR order + per-head max ----------
// one warp per CSR position. Consecutive positions share the same target ->
// the Q row stays in L1 (avg degree ~10 => ~10x less Q traffic).
__global__ __launch_bounds__(256) void k_scores(const float* __restrict__ We)
{
    __shared__ unsigned smax[HEADS];
    const int tid = threadIdx.x;
    if (tid < HEADS) smax[tid] = 0u;
    __syncthreads();

    const int warp = tid >> 5, lane = tid & 31;
    const int p = blockIdx.x * 8 + warp;
    if (p < NE) {
        int src = g_csr_src[p];
        int tgt = g_csr_tgt[p];
        const float4* q = (const float4*)(g_Q + (size_t)tgt * OC);
        const float4* k = (const float4*)(g_K + (size_t)src * OC);
        float4 qa = q[lane], qb = q[lane + 32];
        float4 ka = k[lane], kb = k[lane + 32];
        float d1 = qa.x * ka.x + qa.y * ka.y + qa.z * ka.z + qa.w * ka.w;
        float d2 = qb.x * kb.x + qb.y * kb.y + qb.z * kb.z + qb.w * kb.w;
        #pragma unroll
        for (int o = 8; o; o >>= 1) {
            d1 += __shfl_xor_sync(0xffffffffu, d1, o);
            d2 += __shfl_xor_sync(0xffffffffu, d2, o);
        }
        if ((lane & 15) == 0) {
            int hb = lane >> 4;            // 0 or 1
            float ewv = g_csr_ew[p];
            float s1 = d1 * 0.125f + ewv * We[hb];        // head hb
            float s2 = d2 * 0.125f + ewv * We[hb + 2];    // head hb+2
            s1 = (s1 > 0.0f) ? s1 : 0.2f * s1;            // leaky_relu 0.2
            s2 = (s2 > 0.0f) ? s2 : 0.2f * s2;
            g_S[p * 4 + hb]     = s1;
            g_S[p * 4 + hb + 2] = s2;
            atomicMax(&smax[hb],     fflip(s1));
            atomicMax(&smax[hb + 2], fflip(s2));
        }
    }
    __syncthreads();
    if (tid < HEADS) atomicMax(&g_maxkey[tid], smax[tid]);
}

// ---------------- K5: p = exp(s - m), accumulate Z per head -----------------
__global__ __launch_bounds__(256) void k_exp() {
    float m0 = funflip(g_maxkey[0]), m1 = funflip(g_maxkey[1]);
    float m2 = funflip(g_maxkey[2]), m3 = funflip(g_maxkey[3]);
    float l0 = 0.f, l1 = 0.f, l2 = 0.f, l3 = 0.f;
    for (int e = blockIdx.x * blockDim.x + threadIdx.x; e < NE;
         e += gridDim.x * blockDim.x) {
        float4 s = *(const float4*)&g_S[e * 4];
        float4 p;
        p.x = __expf(s.x - m0);
        p.y = __expf(s.y - m1);
        p.z = __expf(s.z - m2);
        p.w = __expf(s.w - m3);
        *(float4*)&g_S[e * 4] = p;
        l0 += p.x; l1 += p.y; l2 += p.z; l3 += p.w;
    }
    #pragma unroll
    for (int o = 16; o; o >>= 1) {
        l0 += __shfl_xor_sync(0xffffffffu, l0, o);
        l1 += __shfl_xor_sync(0xffffffffu, l1, o);
        l2 += __shfl_xor_sync(0xffffffffu, l2, o);
        l3 += __shfl_xor_sync(0xffffffffu, l3, o);
    }
    __shared__ float part[8][HEADS];
    int warp = threadIdx.x >> 5, lane = threadIdx.x & 31;
    if (lane == 0) { part[warp][0] = l0; part[warp][1] = l1; part[warp][2] = l2; part[warp][3] = l3; }
    __syncthreads();
    if (threadIdx.x < HEADS) {
        float t = 0.f;
        #pragma unroll
        for (int w = 0; w < 8; w++) t += part[w][threadIdx.x];
        atomicAdd(&g_Z[threadIdx.x], t);
    }
}

// ---------------- K6: per-target-node gather-aggregate ----------------------
// one warp per node; streams contiguous csr_src / S, random V row gathers
// unrolled x4 for memory-level parallelism. No float atomics.
__global__ __launch_bounds__(256) void k_agg() {
    const int warp = threadIdx.x >> 5, lane = threadIdx.x & 31;
    const int n = blockIdx.x * 8 + warp;
    if (n >= NN) return;
    const int h1 = lane >> 4;          // 0/1
    const float iz1 = 1.0f / g_Z[h1];
    const float iz2 = 1.0f / g_Z[h1 + 2];
    float4 a1 = make_float4(0.f, 0.f, 0.f, 0.f);
    float4 a2 = make_float4(0.f, 0.f, 0.f, 0.f);
    const int beg = g_offsets[n], end = g_offsets[n + 1];
    const float4* S4 = (const float4*)g_S;
    int j = beg;
    for (; j + 4 <= end; j += 4) {
        int s0 = g_csr_src[j],     s1 = g_csr_src[j + 1];
        int s2 = g_csr_src[j + 2], s3 = g_csr_src[j + 3];
        float4 p0 = S4[j],     p1 = S4[j + 1];
        float4 p2 = S4[j + 2], p3 = S4[j + 3];
        const float4* v0 = (const float4*)(g_V + (size_t)s0 * OC);
        const float4* v1 = (const float4*)(g_V + (size_t)s1 * OC);
        const float4* v2 = (const float4*)(g_V + (size_t)s2 * OC);
        const float4* v3 = (const float4*)(g_V + (size_t)s3 * OC);
        float4 va0 = v0[lane], vb0 = v0[lane + 32];
        float4 va1 = v1[lane], vb1 = v1[lane + 32];
        float4 va2 = v2[lane], vb2 = v2[lane + 32];
        float4 va3 = v3[lane], vb3 = v3[lane + 32];
        float w10 = (lane < 16) ? p0.x : p0.y, w20 = (lane < 16) ? p0.z : p0.w;
        float w11 = (lane < 16) ? p1.x : p1.y, w21 = (lane < 16) ? p1.z : p1.w;
        float w12 = (lane < 16) ? p2.x : p2.y, w22 = (lane < 16) ? p2.z : p2.w;
        float w13 = (lane < 16) ? p3.x : p3.y, w23 = (lane < 16) ? p3.z : p3.w;
        a1.x += w10 * va0.x; a1.y += w10 * va0.y; a1.z += w10 * va0.z; a1.w += w10 * va0.w;
        a2.x += w20 * vb0.x; a2.y += w20 * vb0.y; a2.z += w20 * vb0.z; a2.w += w20 * vb0.w;
        a1.x += w11 * va1.x; a1.y += w11 * va1.y; a1.z += w11 * va1.z; a1.w += w11 * va1.w;
        a2.x += w21 * vb1.x; a2.y += w21 * vb1.y; a2.z += w21 * vb1.z; a2.w += w21 * vb1.w;
        a1.x += w12 * va2.x; a1.y += w12 * va2.y; a1.z += w12 * va2.z; a1.w += w12 * va2.w;
        a2.x += w22 * vb2.x; a2.y += w22 * vb2.y; a2.z += w22 * vb2.z; a2.w += w22 * vb2.w;
        a1.x += w13 * va3.x; a1.y += w13 * va3.y; a1.z += w13 * va3.z; a1.w += w13 * va3.w;
        a2.x += w23 * vb3.x; a2.y += w23 * vb3.y; a2.z += w23 * vb3.z; a2.w += w23 * vb3.w;
    }
    for (; j < end; j++) {
        int s0 = g_csr_src[j];
        float4 p0 = S4[j];
        const float4* v0 = (const float4*)(g_V + (size_t)s0 * OC);
        float4 va0 = v0[lane], vb0 = v0[lane + 32];
        float w10 = (lane < 16) ? p0.x : p0.y;
        float w20 = (lane < 16) ? p0.z : p0.w;
        a1.x += w10 * va0.x; a1.y += w10 * va0.y; a1.z += w10 * va0.z; a1.w += w10 * va0.w;
        a2.x += w20 * vb0.x; a2.y += w20 * vb0.y; a2.z += w20 * vb0.z; a2.w += w20 * vb0.w;
    }
    a1.x *= iz1; a1.y *= iz1; a1.z *= iz1; a1.w *= iz1;
    a2.x *= iz2; a2.y *= iz2; a2.z *= iz2; a2.w *= iz2;
    float* o = g_agg + (size_t)n * OC;
    ((float4*)o)[lane]      = a1;
    ((float4*)o)[lane + 32] = a2;
}

// ---------------- K7: out = agg @ Wout + b_out ------------------------------
// block: 128 rows x 64 cols, 256 threads, 4x8 per thread, f32x2 packed FMA.
// Conflict-free b reads: thread covers cols tx*4 and 32+tx*4.
#define ASW 33
__global__ __launch_bounds__(256) void k_out(
    const float* __restrict__ Wout, const float* __restrict__ bout,
    float* __restrict__ out)
{
    __shared__ __align__(16) float as[128 * ASW];  // ~16.5 KB (padded)
    __shared__ __align__(16) float ws[32 * 64];    // 8 KB
    const int tid  = threadIdx.x;
    const int row0 = blockIdx.x * 128;
    const int ty = tid >> 3;   // 0..31 : rows ty*4..+4
    const int tx = tid & 7;    // 0..7  : cols tx*4 and 32+tx*4

    u64 acc[4][4];
    #pragma unroll
    for (int r = 0; r < 4; r++)
        #pragma unroll
        for (int j = 0; j < 4; j++) acc[r][j] = 0ull;

    for (int kt = 0; kt < OC; kt += 32) {
        __syncthreads();
        for (int i = tid; i < 128 * 32; i += 256) {
            int r = i >> 5, c = i & 31;
            int gr = row0 + r;
            as[r * ASW + c] = (gr < NN) ? g_agg[(size_t)gr * OC + kt + c] : 0.0f;
        }
        for (int i = tid; i < 32 * 64; i += 256) {
            int r = i >> 6, c = i & 63;
            ws[i] = Wout[(kt + r) * OUTC + c];
        }
        __syncthreads();
        #pragma unroll
        for (int k = 0; k < 32; k++) {
            ulonglong2 b0 = *(const ulonglong2*)&ws[k * 64 + tx * 4];
            ulonglong2 b1 = *(const ulonglong2*)&ws[k * 64 + 32 + tx * 4];
            #pragma unroll
            for (int r = 0; r < 4; r++) {
                u64 a = pack_dup(as[(ty * 4 + r) * ASW + k]);
                fma2(acc[r][0], a, b0.x);
                fma2(acc[r][1], a, b0.y);
                fma2(acc[r][2], a, b1.x);
                fma2(acc[r][3], a, b1.y);
            }
        }
    }

    float4 bb0 = *(const float4*)&bout[tx * 4];
    float4 bb1 = *(const float4*)&bout[32 + tx * 4];
    #pragma unroll
    for (int r = 0; r < 4; r++) {
        int gr = row0 + ty * 4 + r;
        if (gr < NN) {
            float2 f0 = unpack2(acc[r][0]), f1 = unpack2(acc[r][1]);
            float2 f2 = unpack2(acc[r][2]), f3 = unpack2(acc[r][3]);
            float4 o0 = make_float4(f0.x + bb0.x, f0.y + bb0.y, f1.x + bb0.z, f1.y + bb0.w);
            float4 o1 = make_float4(f2.x + bb1.x, f2.y + bb1.y, f3.x + bb1.z, f3.y + bb1.w);
            *(float4*)&out[(size_t)gr * OUTC + tx * 4]      = o0;
            *(float4*)&out[(size_t)gr * OUTC + 32 + tx * 4] = o1;
        }
    }
}

// ---------------- launch -----------------------------------------------------
// NOTE: launch #4 is the ncu capture slot -> k_qkv placed 4th to get its profile.
extern "C" void kernel_launch(void* const* d_in, const int* in_sizes, int n_in,
                              void* d_out, int out_size)
{
    const float* x    = (const float*)d_in[0];
    const void*  ei   = d_in[1];                 // int32 or int64 [2, E] (probed)
    const float* ew   = (const float*)d_in[2];
    const float* Wq   = (const float*)d_in[3];
    const float* Wk   = (const float*)d_in[4];
    const float* Wv   = (const float*)d_in[5];
    const float* We   = (const float*)d_in[6];
    const float* Wout = (const float*)d_in[7];
    const float* bout = (const float*)d_in[8];
    float*       out  = (float*)d_out;

    k_init   <<<(NN + 255) / 256, 256>>>(ei);      // 1
    k_decode <<<(NE + 255) / 256, 256>>>(ei);      // 2
    k_scan1  <<<NBLK,            1024>>>();        // 3
    k_qkv    <<<(NN + 63) / 64,   256>>>(x, Wq, Wk, Wv);  // 4  <- profiled
    k_scan2  <<<1,                  1>>>();        // 5
    k_scan3  <<<NBLK,            1024>>>();        // 6
    k_scatter<<<(NE + 255) / 256, 256>>>(ew);      // 7
    k_scores <<<NE / 8,           256>>>(We);      // 8
    k_exp    <<<512,              256>>>();        // 9
    k_agg    <<<(NN + 7) / 8,     256>>>();        // 10
    k_out    <<<(NN + 127) / 128, 256>>>(Wout, bout, out); // 11
}